// round 12
// baseline (speedup 1.0000x reference)
#include <cuda_runtime.h>
#include <cuda_bf16.h>
#include <cstdint>
#include <cstddef>

#define N_FEAT 3072
#define K_LAT  128
#define BATCH  8192
#define CH     64
#define NCH    48          /* 3072 / 64 */
#define MBLK   64
#define GBLK   16          /* gram blocks, 3 chunks each */

// ---------------- device scratch (static — no allocations) ----------------
__device__ float g_Mpart[GBLK * K_LAT * K_LAT];                     // 1 MB gram partials
__device__ float g_M[K_LAT * K_LAT];                                // reduced gram
__device__ float g_consts[2];                                       // [0]=n log2pi+logdetC, [1]=1/sigma^2
__device__ __align__(16) __nv_bfloat16 g_Wt_sw[NCH * K_LAT * CH];   // 768 KB, per-chunk SW128 W^T
__device__ __align__(16) __nv_bfloat16 g_Minv_bf[K_LAT * K_LAT];    // 32 KB, row-major bf16 Minv

static __device__ __forceinline__ uint32_t smem_u32(const void* p) {
    uint32_t a;
    asm("{ .reg .u64 t; cvta.to.shared.u64 t, %1; cvt.u32.u64 %0, t; }" : "=r"(a) : "l"(p));
    return a;
}

#define LDMX4(r, addr) \
    asm volatile("ldmatrix.sync.aligned.m8n8.x4.shared.b16 {%0,%1,%2,%3}, [%4];" \
        : "=r"((r)[0]), "=r"((r)[1]), "=r"((r)[2]), "=r"((r)[3]) : "r"(addr))

#define MMA16816(d, a, b0, b1) \
    asm volatile("mma.sync.aligned.m16n8k16.row.col.f32.bf16.bf16.f32 " \
        "{%0,%1,%2,%3}, {%4,%5,%6,%7}, {%8,%9}, {%0,%1,%2,%3};" \
        : "+f"((d)[0]), "+f"((d)[1]), "+f"((d)[2]), "+f"((d)[3]) \
        : "r"((a)[0]), "r"((a)[1]), "r"((a)[2]), "r"((a)[3]), "r"(b0), "r"(b1))

static __device__ __forceinline__ uint32_t bfx2(float a, float b) {
    __nv_bfloat162 h = __floats2bfloat162_rn(a, b);
    return *reinterpret_cast<uint32_t*>(&h);
}
static __device__ __forceinline__ float2 ubfx2(uint32_t v) {
    float2 r;
    r.x = __uint_as_float(v << 16);
    r.y = __uint_as_float(v & 0xffff0000u);
    return r;
}
static __device__ __forceinline__ unsigned long long pk2(float x, float y) {
    unsigned long long r;
    asm("mov.b64 %0, {%1,%2};" : "=l"(r) : "f"(x), "f"(y));
    return r;
}
static __device__ __forceinline__ float2 upk2(unsigned long long v) {
    float2 r;
    asm("mov.b64 {%0,%1}, %2;" : "=f"(r.x), "=f"(r.y) : "l"(v));
    return r;
}
static __device__ __forceinline__ unsigned long long ffma2(
    unsigned long long a, unsigned long long b, unsigned long long c) {
    unsigned long long d;
    asm("fma.rn.f32x2 %0, %1, %2, %3;" : "=l"(d) : "l"(a), "l"(b), "l"(c));
    return d;
}

// ============ k_gram: build SW128 bf16 W^T chunks + MMA gram partials ============
__global__ __launch_bounds__(512) void k_gram(const float* __restrict__ W) {
    __shared__ __align__(16) unsigned char buf[K_LAT * CH * 2];   // 16 KB, one chunk
    const int t = threadIdx.x, lane = t & 31, wid = t >> 5;
    const int b = blockIdx.x;
    const int wm = wid & 3, wn = wid >> 2;
    const int m0 = wm * 32, n0 = wn * 32;
    const int rA = lane & 15, cA16 = lane >> 4;
    uint32_t aOff[2], aXor[2];
#pragma unroll
    for (int mi = 0; mi < 2; mi++) {
        int r = m0 + mi * 16 + rA;
        aOff[mi] = (uint32_t)(r * 128);
        aXor[mi] = (uint32_t)((r & 7) << 4);
    }
    const uint32_t aCol = (uint32_t)(cA16 * 16);
    const int nB = (lane & 7) + ((lane & 16) ? 8 : 0);
    uint32_t bOff[2];
#pragma unroll
    for (int nj = 0; nj < 2; nj++) bOff[nj] = (uint32_t)((n0 + nj * 16 + nB) * 128);
    const uint32_t bXor = (uint32_t)((lane & 7) << 4);
    const uint32_t bCol = (lane & 8) ? 16u : 0u;
    const uint32_t base = smem_u32(buf);

    float acc[2][4][4];
#pragma unroll
    for (int mi = 0; mi < 2; mi++)
#pragma unroll
        for (int nt = 0; nt < 4; nt++)
#pragma unroll
            for (int e = 0; e < 4; e++) acc[mi][nt][e] = 0.f;

    float vreg[16];
    {
        const float* src = W + (size_t)(b * 3) * CH * K_LAT;
#pragma unroll
        for (int it = 0; it < 16; it++) vreg[it] = src[it * 512 + t];
    }

    for (int cc = 0; cc < 3; cc++) {
        const int ch = b * 3 + cc;
#pragma unroll
        for (int it = 0; it < 16; it++) {
            int l = it * 512 + t;
            int rr = l >> 7, n = l & 127;
            unsigned off = (unsigned)(n * 128 + ((rr * 2) ^ ((n & 7) << 4)));
            *reinterpret_cast<__nv_bfloat16*>(&buf[off]) = __float2bfloat16(vreg[it]);
        }
        __syncthreads();
        if (cc + 1 < 3) {
            const float* src = W + (size_t)(ch + 1) * CH * K_LAT;
#pragma unroll
            for (int it = 0; it < 16; it++) vreg[it] = src[it * 512 + t];
        }
        {
            const uint4* s4 = reinterpret_cast<const uint4*>(buf);
            uint4* d4 = reinterpret_cast<uint4*>(g_Wt_sw) + ch * 1024;
            d4[t] = s4[t];
            d4[512 + t] = s4[512 + t];
        }
#pragma unroll
        for (int ks = 0; ks < 4; ks++) {
            const uint32_t kb = (uint32_t)(ks * 32);
            uint32_t a[2][4], b4[2][4];
#pragma unroll
            for (int mi = 0; mi < 2; mi++)
                LDMX4(a[mi], base + aOff[mi] + ((aCol + kb) ^ aXor[mi]));
#pragma unroll
            for (int nj = 0; nj < 2; nj++)
                LDMX4(b4[nj], base + bOff[nj] + ((bCol + kb) ^ bXor));
#pragma unroll
            for (int mi = 0; mi < 2; mi++)
#pragma unroll
                for (int nt = 0; nt < 4; nt++)
                    MMA16816(acc[mi][nt], a[mi], b4[nt >> 1][2 * (nt & 1)], b4[nt >> 1][2 * (nt & 1) + 1]);
        }
        __syncthreads();
    }
    float* outp = g_Mpart + (size_t)b * (K_LAT * K_LAT);
#pragma unroll
    for (int mi = 0; mi < 2; mi++)
#pragma unroll
        for (int nt = 0; nt < 4; nt++) {
            int m = m0 + mi * 16 + (lane >> 2);
            int n = n0 + nt * 8 + 2 * (lane & 3);
            outp[m * K_LAT + n]     = acc[mi][nt][0];
            outp[m * K_LAT + n + 1] = acc[mi][nt][1];
            outp[(m + 8) * K_LAT + n]     = acc[mi][nt][2];
            outp[(m + 8) * K_LAT + n + 1] = acc[mi][nt][3];
        }
}

// ============ k_reduce: fold 16 partials -> g_M (64 blocks x 256 threads) ============
__global__ __launch_bounds__(256) void k_reduce() {
    int idx = blockIdx.x * 256 + threadIdx.x;    // 0..16383
    float s = 0.f;
#pragma unroll
    for (int p = 0; p < GBLK; p++) s += g_Mpart[p * (K_LAT * K_LAT) + idx];
    g_M[idx] = s;
}

// ============ k_invert: 256-thread packed-f32x2 Gauss-Jordan ============
__global__ __launch_bounds__(256, 1) void k_invert(const float* __restrict__ lv) {
    __shared__ __align__(16) unsigned char smem[3072];
    unsigned long long* rowb = reinterpret_cast<unsigned long long*>(smem);     // [2][64]
    float* colb = reinterpret_cast<float*>(smem + 1024);                         // [2][128]
    float* pivS = reinterpret_cast<float*>(smem + 2048);                         // [128]
    float* redS = reinterpret_cast<float*>(smem + 2560);                         // [4]
    const int t = threadIdx.x, lane = t & 31;
    const int i = t & 127, cB = t >> 7;   // row i, col-half cB (64 cols)
    float lv0 = lv[0];
    float sig2 = expf(lv0);

    float a[64];
    {
        const float4* src = reinterpret_cast<const float4*>(g_M + i * K_LAT + cB * 64);
#pragma unroll
        for (int q = 0; q < 16; q++) {
            float4 v = src[q];
            a[q * 4 + 0] = v.x; a[q * 4 + 1] = v.y;
            a[q * 4 + 2] = v.z; a[q * 4 + 3] = v.w;
        }
    }
    if ((i >> 6) == cB) a[i & 63] += sig2;

    unsigned long long A2[32];
#pragma unroll
    for (int u = 0; u < 32; u++) A2[u] = pk2(a[2 * u], a[2 * u + 1]);

    int buf = 0;
    for (int k = 0; k < 128; k++) {
        if (i == k) {
#pragma unroll
            for (int u = 0; u < 32; u++) rowb[buf * 64 + cB * 32 + u] = A2[u];
        }
        if (cB == (k >> 6)) {
            int u = k & 63;
            float2 pr = upk2(A2[u >> 1]);
            colb[buf * 128 + i] = (u & 1) ? pr.y : pr.x;
        }
        __syncthreads();
        float p = colb[buf * 128 + k];
        float d = 1.0f / p;
        if (t == 0) pivS[k] = p;
        if (i == k) {
#pragma unroll
            for (int u = 0; u < 32; u++) {
                float2 v = upk2(A2[u]);
                A2[u] = pk2(v.x * d, v.y * d);
            }
            if (cB == (k >> 6)) {
                int u = k & 63;
                float2 v = upk2(A2[u >> 1]);
                if (u & 1) v.y = d; else v.x = d;
                A2[u >> 1] = pk2(v.x, v.y);
            }
        } else {
            float nci = -colb[buf * 128 + i] * d;
            unsigned long long n2 = pk2(nci, nci);
#pragma unroll
            for (int u = 0; u < 32; u++)
                A2[u] = ffma2(n2, rowb[buf * 64 + cB * 32 + u], A2[u]);
            if (cB == (k >> 6)) {
                int u = k & 63;
                float2 v = upk2(A2[u >> 1]);
                if (u & 1) v.y = nci; else v.x = nci;
                A2[u >> 1] = pk2(v.x, v.y);
            }
        }
        buf ^= 1;
    }
    {
        uint32_t* dst = reinterpret_cast<uint32_t*>(g_Minv_bf) + (i * K_LAT + cB * 64) / 2;
#pragma unroll
        for (int u = 0; u < 32; u++) {
            float2 v = upk2(A2[u]);
            dst[u] = bfx2(v.x, v.y);
        }
    }
    __syncthreads();
    float ld = 0.f;
    if (t < 128) ld = logf(pivS[t]);
#pragma unroll
    for (int off = 16; off > 0; off >>= 1) ld += __shfl_xor_sync(0xffffffffu, ld, off);
    if (t < 128 && lane == 0) redS[t >> 5] = ld;
    __syncthreads();
    if (t == 0) {
        const float LOG2PI = 1.8378770664093453f;
        float logdet = redS[0] + redS[1] + redS[2] + redS[3];
        g_consts[0] = (float)N_FEAT * LOG2PI + (float)(N_FEAT - K_LAT) * lv0 + logdet;
        g_consts[1] = expf(-lv0);
    }
}

// ============ k_main: EXACT R8 kernel (measured 66 us) ============
// mainloop smem:  A 2x8KB @0, B 2x16KB @16384, mean 12KB @49152, red @61440
// epilogue smem:  Y (pitch 272B, 64 rows) @0, Minv (pitch 272B, 128 rows) @17408
#define SM_A     0
#define SM_B     16384
#define SM_MEAN  49152
#define SM_RED   61440
#define SM_Y     0
#define SM_MI    17408
#define SM_TOTAL 62720

__global__ void __launch_bounds__(256, 2) k_main(const float* __restrict__ ex,
                                                 const float* __restrict__ mean,
                                                 float* __restrict__ out) {
    extern __shared__ __align__(16) unsigned char smem[];
    uint32_t sb = smem_u32(smem);
    const int t = threadIdx.x, lane = t & 31, wid = t >> 5;
    const int wm = wid & 1, wn = wid >> 1;        // warp grid: 2 (M) x 4 (N)
    const int m0 = wm * 32, n0 = wn * 32;

    // cache mean in smem
    float* meanS = reinterpret_cast<float*>(smem + SM_MEAN);
    for (int i = t; i < N_FEAT; i += 256) meanS[i] = mean[i];

    // residual load geometry: 4 threads per row, 16 cols each
    const int row = t >> 2, q = t & 3;
    const float4* exp4 =
        reinterpret_cast<const float4*>(ex + (size_t)(blockIdx.x * MBLK + row) * N_FEAT) + q * 4;
    float4 cur[4];
#pragma unroll
    for (int g = 0; g < 4; g++) cur[g] = exp4[g];

    // ldmatrix lane geometry (SW128, 128B rows)
    const int rA = lane & 15, cA16 = lane >> 4;
    uint32_t aOff[2], aXor[2];
#pragma unroll
    for (int mi = 0; mi < 2; mi++) {
        int r = m0 + mi * 16 + rA;
        aOff[mi] = (uint32_t)(r * 128);
        aXor[mi] = (uint32_t)((r & 7) << 4);
    }
    const uint32_t aCol = (uint32_t)(cA16 * 16);
    const int nB = (lane & 7) + ((lane & 16) ? 8 : 0);
    uint32_t bOff[2];
#pragma unroll
    for (int nj = 0; nj < 2; nj++) bOff[nj] = (uint32_t)((n0 + nj * 16 + nB) * 128);
    const uint32_t bXor = (uint32_t)((lane & 7) << 4);
    const uint32_t bCol = (lane & 8) ? 16u : 0u;

    float acc[2][4][4];
#pragma unroll
    for (int mi = 0; mi < 2; mi++)
#pragma unroll
        for (int nt = 0; nt < 4; nt++)
#pragma unroll
            for (int e = 0; e < 4; e++) acc[mi][nt][e] = 0.f;

    float ssq = 0.f;
    const uint32_t rbase = (uint32_t)(row * 128);
    const uint32_t xr = (uint32_t)((row & 7) << 4);

    for (int c = 0; c < NCH; c++) {
        const int buf = c & 1;
        // B chunk copy (pre-swizzled, L2-resident): 1024 uint4
        {
            const uint4* src = reinterpret_cast<const uint4*>(g_Wt_sw) + c * 1024;
            uint4* dst = reinterpret_cast<uint4*>(smem + SM_B + buf * 16384);
#pragma unroll
            for (int i = 0; i < 4; i++) dst[i * 256 + t] = src[i * 256 + t];
        }
        // A convert: res = ex - mean -> bf16 swizzled; ssq accumulate
        {
            unsigned char* A = smem + SM_A + buf * 8192;
            const float* mS = meanS + c * 64 + q * 16;
#pragma unroll
            for (int g = 0; g < 4; g++) {
                float4 x = cur[g];
                float4 m4 = *reinterpret_cast<const float4*>(mS + g * 4);
                float r0 = x.x - m4.x, r1 = x.y - m4.y, r2 = x.z - m4.z, r3 = x.w - m4.w;
                ssq = fmaf(r0, r0, ssq); ssq = fmaf(r1, r1, ssq);
                ssq = fmaf(r2, r2, ssq); ssq = fmaf(r3, r3, ssq);
                uint32_t off = rbase + (((uint32_t)(q * 32 + g * 8)) ^ xr);
                *reinterpret_cast<uint2*>(A + off) = make_uint2(bfx2(r0, r1), bfx2(r2, r3));
            }
        }
        // prefetch next chunk (overlaps compute via double buffer)
        if (c + 1 < NCH) {
#pragma unroll
            for (int g = 0; g < 4; g++) cur[g] = exp4[(c + 1) * 16 + g];
        }
        __syncthreads();

        const uint32_t A = sb + SM_A + buf * 8192;
        const uint32_t B = sb + SM_B + buf * 16384;
#pragma unroll
        for (int ks = 0; ks < 4; ks++) {
            const uint32_t kb = (uint32_t)(ks * 32);
            uint32_t a[2][4], b4[2][4];
#pragma unroll
            for (int mi = 0; mi < 2; mi++)
                LDMX4(a[mi], A + aOff[mi] + ((aCol + kb) ^ aXor[mi]));
#pragma unroll
            for (int nj = 0; nj < 2; nj++)
                LDMX4(b4[nj], B + bOff[nj] + ((bCol + kb) ^ bXor));
#pragma unroll
            for (int mi = 0; mi < 2; mi++)
#pragma unroll
                for (int nt = 0; nt < 4; nt++)
                    MMA16816(acc[mi][nt], a[mi], b4[nt >> 1][2 * (nt & 1)], b4[nt >> 1][2 * (nt & 1) + 1]);
        }
    }

    // ssq: reduce 4 threads per row
    ssq += __shfl_xor_sync(0xffffffffu, ssq, 1);
    ssq += __shfl_xor_sync(0xffffffffu, ssq, 2);
    float* ssqS = reinterpret_cast<float*>(smem + SM_RED);
    if ((lane & 3) == 0) ssqS[wid * 8 + (lane >> 2)] = ssq;
    __syncthreads();   // all mainloop smem reads done; safe to overwrite with Y/Minv

    // ---- epilogue: stage Y bf16 (pitch 272), copy Minv bf16 (pitch 272) ----
#pragma unroll
    for (int mi = 0; mi < 2; mi++)
#pragma unroll
        for (int nt = 0; nt < 4; nt++) {
            int m = m0 + mi * 16 + (lane >> 2);
            int n = n0 + nt * 8 + 2 * (lane & 3);
            *reinterpret_cast<uint32_t*>(smem + SM_Y + m * 272 + n * 2) =
                bfx2(acc[mi][nt][0], acc[mi][nt][1]);
            *reinterpret_cast<uint32_t*>(smem + SM_Y + (m + 8) * 272 + n * 2) =
                bfx2(acc[mi][nt][2], acc[mi][nt][3]);
        }
    {
        const uint4* msrc = reinterpret_cast<const uint4*>(g_Minv_bf);
#pragma unroll
        for (int i = 0; i < 8; i++) {
            int idx = i * 256 + t;
            int r = idx >> 4, cc = idx & 15;
            *reinterpret_cast<uint4*>(smem + SM_MI + r * 272 + cc * 16) = msrc[idx];
        }
    }
    __syncthreads();

    // ---- second GEMM: Q = Y(64x128) @ Minv(128x128) ----
    float acc2[2][4][4];
#pragma unroll
    for (int mi = 0; mi < 2; mi++)
#pragma unroll
        for (int nt = 0; nt < 4; nt++)
#pragma unroll
            for (int e = 0; e < 4; e++) acc2[mi][nt][e] = 0.f;

    uint32_t yRow[2], miRow[2];
#pragma unroll
    for (int mi = 0; mi < 2; mi++)
        yRow[mi] = (uint32_t)(SM_Y + (m0 + mi * 16 + rA) * 272) + aCol;
#pragma unroll
    for (int nj = 0; nj < 2; nj++)
        miRow[nj] = (uint32_t)(SM_MI + (n0 + nj * 16 + nB) * 272) + bCol;

#pragma unroll
    for (int ks = 0; ks < 8; ks++) {
        const uint32_t kb = (uint32_t)(ks * 32);
        uint32_t a[2][4], b4[2][4];
#pragma unroll
        for (int mi = 0; mi < 2; mi++) LDMX4(a[mi], sb + yRow[mi] + kb);
#pragma unroll
        for (int nj = 0; nj < 2; nj++) LDMX4(b4[nj], sb + miRow[nj] + kb);
#pragma unroll
        for (int mi = 0; mi < 2; mi++)
#pragma unroll
            for (int nt = 0; nt < 4; nt++)
                MMA16816(acc2[mi][nt], a[mi], b4[nt >> 1][2 * (nt & 1)], b4[nt >> 1][2 * (nt & 1) + 1]);
    }

    // ---- dot[m] = sum_j Y[m][j] * Q[m][j] (Y re-read with FULL A-frag addressing) ----
    float* ssqS2 = reinterpret_cast<float*>(smem + SM_RED);
    float* dotS = ssqS2 + 64;     // [4][64]
#pragma unroll
    for (int mi = 0; mi < 2; mi++) {
        float dd0 = 0.f, dd1 = 0.f;
#pragma unroll
        for (int jc = 0; jc < 2; jc++) {
            uint32_t ya[4];
            LDMX4(ya, sb + yRow[mi] + (uint32_t)(n0 * 2 + jc * 32));
#pragma unroll
            for (int h = 0; h < 2; h++) {
                int nt = jc * 2 + h;
                float2 y0 = ubfx2(ya[h * 2 + 0]);
                float2 y1 = ubfx2(ya[h * 2 + 1]);
                dd0 += acc2[mi][nt][0] * y0.x + acc2[mi][nt][1] * y0.y;
                dd1 += acc2[mi][nt][2] * y1.x + acc2[mi][nt][3] * y1.y;
            }
        }
        dd0 += __shfl_xor_sync(0xffffffffu, dd0, 1);
        dd0 += __shfl_xor_sync(0xffffffffu, dd0, 2);
        dd1 += __shfl_xor_sync(0xffffffffu, dd1, 1);
        dd1 += __shfl_xor_sync(0xffffffffu, dd1, 2);
        if ((lane & 3) == 0) {
            int m = m0 + mi * 16 + (lane >> 2);
            dotS[wn * 64 + m] = dd0;
            dotS[wn * 64 + m + 8] = dd1;
        }
    }
    __syncthreads();

    if (t < MBLK) {
        float dot = dotS[t] + dotS[64 + t] + dotS[128 + t] + dotS[192 + t];
        float c0 = g_consts[0], is2 = g_consts[1];
        out[blockIdx.x * MBLK + t] = -0.5f * (c0 + (ssqS2[t] - dot) * is2);
    }
}

// ---------------- launch ----------------
extern "C" void kernel_launch(void* const* d_in, const int* in_sizes, int n_in,
                              void* d_out, int out_size) {
    const float* ex = nullptr;
    const float* W = nullptr;
    const float* lv = nullptr;
    const float* mean = nullptr;
    for (int t = 0; t < n_in; t++) {
        if (in_sizes[t] == BATCH * N_FEAT)      ex   = (const float*)d_in[t];
        else if (in_sizes[t] == N_FEAT * K_LAT) W    = (const float*)d_in[t];
        else if (in_sizes[t] == N_FEAT)         mean = (const float*)d_in[t];
        else if (in_sizes[t] == 1)              lv   = (const float*)d_in[t];
    }
    float* out = (float*)d_out;

    cudaFuncSetAttribute(k_main, cudaFuncAttributeMaxDynamicSharedMemorySize, SM_TOTAL);

    k_gram<<<GBLK, 512>>>(W);
    k_reduce<<<K_LAT * K_LAT / 256, 256>>>();
    k_invert<<<1, 256>>>(lv);
    k_main<<<BATCH / MBLK, 256, SM_TOTAL>>>(ex, mean, out);
}

// round 14
// speedup vs baseline: 1.5145x; 1.5145x over previous
#include <cuda_runtime.h>
#include <cuda_bf16.h>
#include <cstdint>
#include <cstddef>

#define N_FEAT 3072
#define K_LAT  128
#define BATCH  8192
#define CH     64
#define NCH    48          /* 3072 / 64 */
#define MBLK   64
#define GBLK   16          /* gram blocks, 3 chunks each */

// ---------------- device scratch (static — no allocations) ----------------
__device__ float g_Mpart[GBLK * K_LAT * K_LAT];                     // 1 MB gram partials
__device__ float g_M[K_LAT * K_LAT];                                // reduced gram
__device__ float g_consts[2];                                       // [0]=n log2pi+logdetC, [1]=1/sigma^2
__device__ __align__(16) __nv_bfloat16 g_Wt_sw[NCH * K_LAT * CH];   // 768 KB, per-chunk SW128 W^T
__device__ __align__(16) __nv_bfloat16 g_Minv_bf[K_LAT * K_LAT];    // 32 KB, row-major bf16 Minv

static __device__ __forceinline__ uint32_t smem_u32(const void* p) {
    uint32_t a;
    asm("{ .reg .u64 t; cvta.to.shared.u64 t, %1; cvt.u32.u64 %0, t; }" : "=r"(a) : "l"(p));
    return a;
}

#define LDMX4(r, addr) \
    asm volatile("ldmatrix.sync.aligned.m8n8.x4.shared.b16 {%0,%1,%2,%3}, [%4];" \
        : "=r"((r)[0]), "=r"((r)[1]), "=r"((r)[2]), "=r"((r)[3]) : "r"(addr))

#define MMA16816(d, a, b0, b1) \
    asm volatile("mma.sync.aligned.m16n8k16.row.col.f32.bf16.bf16.f32 " \
        "{%0,%1,%2,%3}, {%4,%5,%6,%7}, {%8,%9}, {%0,%1,%2,%3};" \
        : "+f"((d)[0]), "+f"((d)[1]), "+f"((d)[2]), "+f"((d)[3]) \
        : "r"((a)[0]), "r"((a)[1]), "r"((a)[2]), "r"((a)[3]), "r"(b0), "r"(b1))

static __device__ __forceinline__ uint32_t bfx2(float a, float b) {
    __nv_bfloat162 h = __floats2bfloat162_rn(a, b);
    return *reinterpret_cast<uint32_t*>(&h);
}
static __device__ __forceinline__ float2 ubfx2(uint32_t v) {
    float2 r;
    r.x = __uint_as_float(v << 16);
    r.y = __uint_as_float(v & 0xffff0000u);
    return r;
}
static __device__ __forceinline__ unsigned long long pk2(float x, float y) {
    unsigned long long r;
    asm("mov.b64 %0, {%1,%2};" : "=l"(r) : "f"(x), "f"(y));
    return r;
}
static __device__ __forceinline__ float2 upk2(unsigned long long v) {
    float2 r;
    asm("mov.b64 {%0,%1}, %2;" : "=f"(r.x), "=f"(r.y) : "l"(v));
    return r;
}
static __device__ __forceinline__ unsigned long long ffma2(
    unsigned long long a, unsigned long long b, unsigned long long c) {
    unsigned long long d;
    asm("fma.rn.f32x2 %0, %1, %2, %3;" : "=l"(d) : "l"(a), "l"(b), "l"(c));
    return d;
}

// ============ k_gram: build SW128 bf16 W^T chunks + MMA gram partials ============
__global__ __launch_bounds__(512) void k_gram(const float* __restrict__ W) {
    __shared__ __align__(16) unsigned char buf[K_LAT * CH * 2];   // 16 KB, one chunk
    const int t = threadIdx.x, lane = t & 31, wid = t >> 5;
    const int b = blockIdx.x;
    const int wm = wid & 3, wn = wid >> 2;
    const int m0 = wm * 32, n0 = wn * 32;
    const int rA = lane & 15, cA16 = lane >> 4;
    uint32_t aOff[2], aXor[2];
#pragma unroll
    for (int mi = 0; mi < 2; mi++) {
        int r = m0 + mi * 16 + rA;
        aOff[mi] = (uint32_t)(r * 128);
        aXor[mi] = (uint32_t)((r & 7) << 4);
    }
    const uint32_t aCol = (uint32_t)(cA16 * 16);
    const int nB = (lane & 7) + ((lane & 16) ? 8 : 0);
    uint32_t bOff[2];
#pragma unroll
    for (int nj = 0; nj < 2; nj++) bOff[nj] = (uint32_t)((n0 + nj * 16 + nB) * 128);
    const uint32_t bXor = (uint32_t)((lane & 7) << 4);
    const uint32_t bCol = (lane & 8) ? 16u : 0u;
    const uint32_t base = smem_u32(buf);

    float acc[2][4][4];
#pragma unroll
    for (int mi = 0; mi < 2; mi++)
#pragma unroll
        for (int nt = 0; nt < 4; nt++)
#pragma unroll
            for (int e = 0; e < 4; e++) acc[mi][nt][e] = 0.f;

    float vreg[16];
    {
        const float* src = W + (size_t)(b * 3) * CH * K_LAT;
#pragma unroll
        for (int it = 0; it < 16; it++) vreg[it] = src[it * 512 + t];
    }

    for (int cc = 0; cc < 3; cc++) {
        const int ch = b * 3 + cc;
#pragma unroll
        for (int it = 0; it < 16; it++) {
            int l = it * 512 + t;
            int rr = l >> 7, n = l & 127;
            unsigned off = (unsigned)(n * 128 + ((rr * 2) ^ ((n & 7) << 4)));
            *reinterpret_cast<__nv_bfloat16*>(&buf[off]) = __float2bfloat16(vreg[it]);
        }
        __syncthreads();
        if (cc + 1 < 3) {
            const float* src = W + (size_t)(ch + 1) * CH * K_LAT;
#pragma unroll
            for (int it = 0; it < 16; it++) vreg[it] = src[it * 512 + t];
        }
        {
            const uint4* s4 = reinterpret_cast<const uint4*>(buf);
            uint4* d4 = reinterpret_cast<uint4*>(g_Wt_sw) + ch * 1024;
            d4[t] = s4[t];
            d4[512 + t] = s4[512 + t];
        }
#pragma unroll
        for (int ks = 0; ks < 4; ks++) {
            const uint32_t kb = (uint32_t)(ks * 32);
            uint32_t a[2][4], b4[2][4];
#pragma unroll
            for (int mi = 0; mi < 2; mi++)
                LDMX4(a[mi], base + aOff[mi] + ((aCol + kb) ^ aXor[mi]));
#pragma unroll
            for (int nj = 0; nj < 2; nj++)
                LDMX4(b4[nj], base + bOff[nj] + ((bCol + kb) ^ bXor));
#pragma unroll
            for (int mi = 0; mi < 2; mi++)
#pragma unroll
                for (int nt = 0; nt < 4; nt++)
                    MMA16816(acc[mi][nt], a[mi], b4[nt >> 1][2 * (nt & 1)], b4[nt >> 1][2 * (nt & 1) + 1]);
        }
        __syncthreads();
    }
    float* outp = g_Mpart + (size_t)b * (K_LAT * K_LAT);
#pragma unroll
    for (int mi = 0; mi < 2; mi++)
#pragma unroll
        for (int nt = 0; nt < 4; nt++) {
            int m = m0 + mi * 16 + (lane >> 2);
            int n = n0 + nt * 8 + 2 * (lane & 3);
            outp[m * K_LAT + n]     = acc[mi][nt][0];
            outp[m * K_LAT + n + 1] = acc[mi][nt][1];
            outp[(m + 8) * K_LAT + n]     = acc[mi][nt][2];
            outp[(m + 8) * K_LAT + n + 1] = acc[mi][nt][3];
        }
}

// ============ k_reduce: fold 16 partials -> g_M (64 blocks x 256 threads) ============
__global__ __launch_bounds__(256) void k_reduce() {
    int idx = blockIdx.x * 256 + threadIdx.x;    // 0..16383
    float s = 0.f;
#pragma unroll
    for (int p = 0; p < GBLK; p++) s += g_Mpart[p * (K_LAT * K_LAT) + idx];
    g_M[idx] = s;
}

// ============ k_invert: 1024-thread packed-f32x2 Gauss-Jordan ============
// Thread (i, c8): row i, cols [16*c8, 16*c8+16) as 8 packed f32x2 REGISTERS.
// NO dynamic register-array indexing anywhere (that forces local-mem demotion —
// the R10-R12 k_invert bug). Element-k handling:
//   - row k is published with element k replaced by (1+p); consumer rows then
//     get column k right for free: A_old + nci*(1+p) = nci (nci = -A_old/p).
//   - pivot row scales by d=1/p and patches its diagonal via static-index
//     predicated unroll.
__global__ __launch_bounds__(1024, 1) void k_invert(const float* __restrict__ lv) {
    __shared__ __align__(16) unsigned long long rowb[2][64];
    __shared__ float colb[2][128];
    __shared__ float pivS[128];
    __shared__ float redS[4];
    const int t = threadIdx.x, lane = t & 31;
    const int i = t & 127, c8 = t >> 7;        // c8 in 0..7
    float lv0 = lv[0];
    float sig2 = expf(lv0);

    unsigned long long A2[8];
    {
        const float4* src = reinterpret_cast<const float4*>(g_M + i * K_LAT + c8 * 16);
#pragma unroll
        for (int q = 0; q < 4; q++) {
            float4 v = src[q];
            A2[2 * q]     = pk2(v.x, v.y);
            A2[2 * q + 1] = pk2(v.z, v.w);
        }
    }
    if ((i >> 4) == c8) {
        int kc = i & 15;
#pragma unroll
        for (int u = 0; u < 8; u++) {
            float2 v = upk2(A2[u]);
            if (2 * u == kc)     v.x += sig2;
            if (2 * u + 1 == kc) v.y += sig2;
            A2[u] = pk2(v.x, v.y);
        }
    }

    int buf = 0;
    for (int k = 0; k < 128; k++) {
        const int kh = k >> 4, kc = k & 15, kp = kc >> 1;
        // publish colb: old column k (threads whose slice holds col k)
        float myk = 0.f;
        if (c8 == kh) {
#pragma unroll
            for (int u = 0; u < 8; u++) {
                float2 v = upk2(A2[u]);
                if (2 * u == kc)     myk = v.x;
                if (2 * u + 1 == kc) myk = v.y;
            }
            colb[buf][i] = myk;
        }
        // publish rowb: old row k, element k replaced by (1 + p)
        if (i == k) {
#pragma unroll
            for (int u = 0; u < 8; u++) {
                unsigned long long val = A2[u];
                if (c8 == kh && u == kp) {
                    float2 v = upk2(val);
                    if (kc & 1) v.y = 1.0f + myk; else v.x = 1.0f + myk;
                    val = pk2(v.x, v.y);
                }
                rowb[buf][c8 * 8 + u] = val;
            }
        }
        __syncthreads();
        float p = colb[buf][k];
        float d = 1.0f / p;
        if (t == 0) pivS[k] = p;
        if (i == k) {
#pragma unroll
            for (int u = 0; u < 8; u++) {
                float2 v = upk2(A2[u]);
                float nx = v.x * d, ny = v.y * d;
                if (c8 == kh) {
                    if (2 * u == kc)     nx = d;
                    if (2 * u + 1 == kc) ny = d;
                }
                A2[u] = pk2(nx, ny);
            }
        } else {
            float nci = -colb[buf][i] * d;
            unsigned long long n2 = pk2(nci, nci);
#pragma unroll
            for (int u = 0; u < 8; u++)
                A2[u] = ffma2(n2, rowb[buf][c8 * 8 + u], A2[u]);
        }
        buf ^= 1;
    }
    // emit bf16 Minv (row-major)
    {
        uint32_t* dst = reinterpret_cast<uint32_t*>(g_Minv_bf) + (i * K_LAT + c8 * 16) / 2;
#pragma unroll
        for (int u = 0; u < 8; u++) {
            float2 v = upk2(A2[u]);
            dst[u] = bfx2(v.x, v.y);
        }
    }
    __syncthreads();
    float ld = 0.f;
    if (t < 128) ld = logf(pivS[t]);
#pragma unroll
    for (int off = 16; off > 0; off >>= 1) ld += __shfl_xor_sync(0xffffffffu, ld, off);
    if (t < 128 && lane == 0) redS[t >> 5] = ld;
    __syncthreads();
    if (t == 0) {
        const float LOG2PI = 1.8378770664093453f;
        float logdet = redS[0] + redS[1] + redS[2] + redS[3];
        g_consts[0] = (float)N_FEAT * LOG2PI + (float)(N_FEAT - K_LAT) * lv0 + logdet;
        g_consts[1] = expf(-lv0);
    }
}

// ============ k_main: EXACT R8/R12 kernel (measured 66 us, regs 124) ============
// mainloop smem:  A 2x8KB @0, B 2x16KB @16384, mean 12KB @49152, red @61440
// epilogue smem:  Y (pitch 272B, 64 rows) @0, Minv (pitch 272B, 128 rows) @17408
#define SM_A     0
#define SM_B     16384
#define SM_MEAN  49152
#define SM_RED   61440
#define SM_Y     0
#define SM_MI    17408
#define SM_TOTAL 62720

__global__ void __launch_bounds__(256, 2) k_main(const float* __restrict__ ex,
                                                 const float* __restrict__ mean,
                                                 float* __restrict__ out) {
    extern __shared__ __align__(16) unsigned char smem[];
    uint32_t sb = smem_u32(smem);
    const int t = threadIdx.x, lane = t & 31, wid = t >> 5;
    const int wm = wid & 1, wn = wid >> 1;        // warp grid: 2 (M) x 4 (N)
    const int m0 = wm * 32, n0 = wn * 32;

    // cache mean in smem
    float* meanS = reinterpret_cast<float*>(smem + SM_MEAN);
    for (int i = t; i < N_FEAT; i += 256) meanS[i] = mean[i];

    // residual load geometry: 4 threads per row, 16 cols each
    const int row = t >> 2, q = t & 3;
    const float4* exp4 =
        reinterpret_cast<const float4*>(ex + (size_t)(blockIdx.x * MBLK + row) * N_FEAT) + q * 4;
    float4 cur[4];
#pragma unroll
    for (int g = 0; g < 4; g++) cur[g] = exp4[g];

    // ldmatrix lane geometry (SW128, 128B rows)
    const int rA = lane & 15, cA16 = lane >> 4;
    uint32_t aOff[2], aXor[2];
#pragma unroll
    for (int mi = 0; mi < 2; mi++) {
        int r = m0 + mi * 16 + rA;
        aOff[mi] = (uint32_t)(r * 128);
        aXor[mi] = (uint32_t)((r & 7) << 4);
    }
    const uint32_t aCol = (uint32_t)(cA16 * 16);
    const int nB = (lane & 7) + ((lane & 16) ? 8 : 0);
    uint32_t bOff[2];
#pragma unroll
    for (int nj = 0; nj < 2; nj++) bOff[nj] = (uint32_t)((n0 + nj * 16 + nB) * 128);
    const uint32_t bXor = (uint32_t)((lane & 7) << 4);
    const uint32_t bCol = (lane & 8) ? 16u : 0u;

    float acc[2][4][4];
#pragma unroll
    for (int mi = 0; mi < 2; mi++)
#pragma unroll
        for (int nt = 0; nt < 4; nt++)
#pragma unroll
            for (int e = 0; e < 4; e++) acc[mi][nt][e] = 0.f;

    float ssq = 0.f;
    const uint32_t rbase = (uint32_t)(row * 128);
    const uint32_t xr = (uint32_t)((row & 7) << 4);

    for (int c = 0; c < NCH; c++) {
        const int buf = c & 1;
        // B chunk copy (pre-swizzled, L2-resident): 1024 uint4
        {
            const uint4* src = reinterpret_cast<const uint4*>(g_Wt_sw) + c * 1024;
            uint4* dst = reinterpret_cast<uint4*>(smem + SM_B + buf * 16384);
#pragma unroll
            for (int i = 0; i < 4; i++) dst[i * 256 + t] = src[i * 256 + t];
        }
        // A convert: res = ex - mean -> bf16 swizzled; ssq accumulate
        {
            unsigned char* A = smem + SM_A + buf * 8192;
            const float* mS = meanS + c * 64 + q * 16;
#pragma unroll
            for (int g = 0; g < 4; g++) {
                float4 x = cur[g];
                float4 m4 = *reinterpret_cast<const float4*>(mS + g * 4);
                float r0 = x.x - m4.x, r1 = x.y - m4.y, r2 = x.z - m4.z, r3 = x.w - m4.w;
                ssq = fmaf(r0, r0, ssq); ssq = fmaf(r1, r1, ssq);
                ssq = fmaf(r2, r2, ssq); ssq = fmaf(r3, r3, ssq);
                uint32_t off = rbase + (((uint32_t)(q * 32 + g * 8)) ^ xr);
                *reinterpret_cast<uint2*>(A + off) = make_uint2(bfx2(r0, r1), bfx2(r2, r3));
            }
        }
        // prefetch next chunk (overlaps compute via double buffer)
        if (c + 1 < NCH) {
#pragma unroll
            for (int g = 0; g < 4; g++) cur[g] = exp4[(c + 1) * 16 + g];
        }
        __syncthreads();

        const uint32_t A = sb + SM_A + buf * 8192;
        const uint32_t B = sb + SM_B + buf * 16384;
#pragma unroll
        for (int ks = 0; ks < 4; ks++) {
            const uint32_t kb = (uint32_t)(ks * 32);
            uint32_t a[2][4], b4[2][4];
#pragma unroll
            for (int mi = 0; mi < 2; mi++)
                LDMX4(a[mi], A + aOff[mi] + ((aCol + kb) ^ aXor[mi]));
#pragma unroll
            for (int nj = 0; nj < 2; nj++)
                LDMX4(b4[nj], B + bOff[nj] + ((bCol + kb) ^ bXor));
#pragma unroll
            for (int mi = 0; mi < 2; mi++)
#pragma unroll
                for (int nt = 0; nt < 4; nt++)
                    MMA16816(acc[mi][nt], a[mi], b4[nt >> 1][2 * (nt & 1)], b4[nt >> 1][2 * (nt & 1) + 1]);
        }
    }

    // ssq: reduce 4 threads per row
    ssq += __shfl_xor_sync(0xffffffffu, ssq, 1);
    ssq += __shfl_xor_sync(0xffffffffu, ssq, 2);
    float* ssqS = reinterpret_cast<float*>(smem + SM_RED);
    if ((lane & 3) == 0) ssqS[wid * 8 + (lane >> 2)] = ssq;
    __syncthreads();   // all mainloop smem reads done; safe to overwrite with Y/Minv

    // ---- epilogue: stage Y bf16 (pitch 272), copy Minv bf16 (pitch 272) ----
#pragma unroll
    for (int mi = 0; mi < 2; mi++)
#pragma unroll
        for (int nt = 0; nt < 4; nt++) {
            int m = m0 + mi * 16 + (lane >> 2);
            int n = n0 + nt * 8 + 2 * (lane & 3);
            *reinterpret_cast<uint32_t*>(smem + SM_Y + m * 272 + n * 2) =
                bfx2(acc[mi][nt][0], acc[mi][nt][1]);
            *reinterpret_cast<uint32_t*>(smem + SM_Y + (m + 8) * 272 + n * 2) =
                bfx2(acc[mi][nt][2], acc[mi][nt][3]);
        }
    {
        const uint4* msrc = reinterpret_cast<const uint4*>(g_Minv_bf);
#pragma unroll
        for (int i = 0; i < 8; i++) {
            int idx = i * 256 + t;
            int r = idx >> 4, cc = idx & 15;
            *reinterpret_cast<uint4*>(smem + SM_MI + r * 272 + cc * 16) = msrc[idx];
        }
    }
    __syncthreads();

    // ---- second GEMM: Q = Y(64x128) @ Minv(128x128) ----
    float acc2[2][4][4];
#pragma unroll
    for (int mi = 0; mi < 2; mi++)
#pragma unroll
        for (int nt = 0; nt < 4; nt++)
#pragma unroll
            for (int e = 0; e < 4; e++) acc2[mi][nt][e] = 0.f;

    uint32_t yRow[2], miRow[2];
#pragma unroll
    for (int mi = 0; mi < 2; mi++)
        yRow[mi] = (uint32_t)(SM_Y + (m0 + mi * 16 + rA) * 272) + aCol;
#pragma unroll
    for (int nj = 0; nj < 2; nj++)
        miRow[nj] = (uint32_t)(SM_MI + (n0 + nj * 16 + nB) * 272) + bCol;

#pragma unroll
    for (int ks = 0; ks < 8; ks++) {
        const uint32_t kb = (uint32_t)(ks * 32);
        uint32_t a[2][4], b4[2][4];
#pragma unroll
        for (int mi = 0; mi < 2; mi++) LDMX4(a[mi], sb + yRow[mi] + kb);
#pragma unroll
        for (int nj = 0; nj < 2; nj++) LDMX4(b4[nj], sb + miRow[nj] + kb);
#pragma unroll
        for (int mi = 0; mi < 2; mi++)
#pragma unroll
            for (int nt = 0; nt < 4; nt++)
                MMA16816(acc2[mi][nt], a[mi], b4[nt >> 1][2 * (nt & 1)], b4[nt >> 1][2 * (nt & 1) + 1]);
    }

    // ---- dot[m] = sum_j Y[m][j] * Q[m][j] (Y re-read with FULL A-frag addressing) ----
    float* ssqS2 = reinterpret_cast<float*>(smem + SM_RED);
    float* dotS = ssqS2 + 64;     // [4][64]
#pragma unroll
    for (int mi = 0; mi < 2; mi++) {
        float dd0 = 0.f, dd1 = 0.f;
#pragma unroll
        for (int jc = 0; jc < 2; jc++) {
            uint32_t ya[4];
            LDMX4(ya, sb + yRow[mi] + (uint32_t)(n0 * 2 + jc * 32));
#pragma unroll
            for (int h = 0; h < 2; h++) {
                int nt = jc * 2 + h;
                float2 y0 = ubfx2(ya[h * 2 + 0]);
                float2 y1 = ubfx2(ya[h * 2 + 1]);
                dd0 += acc2[mi][nt][0] * y0.x + acc2[mi][nt][1] * y0.y;
                dd1 += acc2[mi][nt][2] * y1.x + acc2[mi][nt][3] * y1.y;
            }
        }
        dd0 += __shfl_xor_sync(0xffffffffu, dd0, 1);
        dd0 += __shfl_xor_sync(0xffffffffu, dd0, 2);
        dd1 += __shfl_xor_sync(0xffffffffu, dd1, 1);
        dd1 += __shfl_xor_sync(0xffffffffu, dd1, 2);
        if ((lane & 3) == 0) {
            int m = m0 + mi * 16 + (lane >> 2);
            dotS[wn * 64 + m] = dd0;
            dotS[wn * 64 + m + 8] = dd1;
        }
    }
    __syncthreads();

    if (t < MBLK) {
        float dot = dotS[t] + dotS[64 + t] + dotS[128 + t] + dotS[192 + t];
        float c0 = g_consts[0], is2 = g_consts[1];
        out[blockIdx.x * MBLK + t] = -0.5f * (c0 + (ssqS2[t] - dot) * is2);
    }
}

// ---------------- launch ----------------
extern "C" void kernel_launch(void* const* d_in, const int* in_sizes, int n_in,
                              void* d_out, int out_size) {
    const float* ex = nullptr;
    const float* W = nullptr;
    const float* lv = nullptr;
    const float* mean = nullptr;
    for (int t = 0; t < n_in; t++) {
        if (in_sizes[t] == BATCH * N_FEAT)      ex   = (const float*)d_in[t];
        else if (in_sizes[t] == N_FEAT * K_LAT) W    = (const float*)d_in[t];
        else if (in_sizes[t] == N_FEAT)         mean = (const float*)d_in[t];
        else if (in_sizes[t] == 1)              lv   = (const float*)d_in[t];
    }
    float* out = (float*)d_out;

    cudaFuncSetAttribute(k_main, cudaFuncAttributeMaxDynamicSharedMemorySize, SM_TOTAL);

    k_gram<<<GBLK, 512>>>(W);
    k_reduce<<<K_LAT * K_LAT / 256, 256>>>();
    k_invert<<<1, 1024>>>(lv);
    k_main<<<BATCH / MBLK, 256, SM_TOTAL>>>(ex, mean, out);
}

// round 15
// speedup vs baseline: 2.0853x; 1.3769x over previous
#include <cuda_runtime.h>
#include <cuda_bf16.h>
#include <cstdint>
#include <cstddef>

#define N_FEAT 3072
#define K_LAT  128
#define BATCH  8192
#define CH     64
#define NCH    48          /* 3072 / 64 */
#define MBLK   64
#define GBLK   16          /* gram blocks, 3 chunks each */

// ---------------- device scratch (static — no allocations) ----------------
__device__ float g_Mpart[GBLK * K_LAT * K_LAT];                     // 1 MB gram partials
__device__ float g_M[K_LAT * K_LAT];                                // reduced gram
__device__ float g_consts[2];                                       // [0]=n log2pi+logdetC, [1]=1/sigma^2
__device__ __align__(16) __nv_bfloat16 g_Wt_sw[NCH * K_LAT * CH];   // 768 KB, per-chunk SW128 W^T
__device__ __align__(16) __nv_bfloat16 g_Minv_bf[K_LAT * K_LAT];    // 32 KB, row-major bf16 Minv

static __device__ __forceinline__ uint32_t smem_u32(const void* p) {
    uint32_t a;
    asm("{ .reg .u64 t; cvta.to.shared.u64 t, %1; cvt.u32.u64 %0, t; }" : "=r"(a) : "l"(p));
    return a;
}

#define LDMX4(r, addr) \
    asm volatile("ldmatrix.sync.aligned.m8n8.x4.shared.b16 {%0,%1,%2,%3}, [%4];" \
        : "=r"((r)[0]), "=r"((r)[1]), "=r"((r)[2]), "=r"((r)[3]) : "r"(addr))

#define MMA16816(d, a, b0, b1) \
    asm volatile("mma.sync.aligned.m16n8k16.row.col.f32.bf16.bf16.f32 " \
        "{%0,%1,%2,%3}, {%4,%5,%6,%7}, {%8,%9}, {%0,%1,%2,%3};" \
        : "+f"((d)[0]), "+f"((d)[1]), "+f"((d)[2]), "+f"((d)[3]) \
        : "r"((a)[0]), "r"((a)[1]), "r"((a)[2]), "r"((a)[3]), "r"(b0), "r"(b1))

static __device__ __forceinline__ uint32_t bfx2(float a, float b) {
    __nv_bfloat162 h = __floats2bfloat162_rn(a, b);
    return *reinterpret_cast<uint32_t*>(&h);
}
static __device__ __forceinline__ float2 ubfx2(uint32_t v) {
    float2 r;
    r.x = __uint_as_float(v << 16);
    r.y = __uint_as_float(v & 0xffff0000u);
    return r;
}
static __device__ __forceinline__ unsigned long long pk2(float x, float y) {
    unsigned long long r;
    asm("mov.b64 %0, {%1,%2};" : "=l"(r) : "f"(x), "f"(y));
    return r;
}
static __device__ __forceinline__ float2 upk2(unsigned long long v) {
    float2 r;
    asm("mov.b64 {%0,%1}, %2;" : "=f"(r.x), "=f"(r.y) : "l"(v));
    return r;
}
static __device__ __forceinline__ unsigned long long ffma2(
    unsigned long long a, unsigned long long b, unsigned long long c) {
    unsigned long long d;
    asm("fma.rn.f32x2 %0, %1, %2, %3;" : "=l"(d) : "l"(a), "l"(b), "l"(c));
    return d;
}
static __device__ __forceinline__ unsigned long long mul2(
    unsigned long long a, unsigned long long b) {
    unsigned long long d;
    asm("mul.rn.f32x2 %0, %1, %2;" : "=l"(d) : "l"(a), "l"(b));
    return d;
}

// ============ k_gram: build SW128 bf16 W^T chunks + MMA gram partials ============
__global__ __launch_bounds__(512) void k_gram(const float* __restrict__ W) {
    __shared__ __align__(16) unsigned char buf[K_LAT * CH * 2];   // 16 KB, one chunk
    const int t = threadIdx.x, lane = t & 31, wid = t >> 5;
    const int b = blockIdx.x;
    const int wm = wid & 3, wn = wid >> 2;
    const int m0 = wm * 32, n0 = wn * 32;
    const int rA = lane & 15, cA16 = lane >> 4;
    uint32_t aOff[2], aXor[2];
#pragma unroll
    for (int mi = 0; mi < 2; mi++) {
        int r = m0 + mi * 16 + rA;
        aOff[mi] = (uint32_t)(r * 128);
        aXor[mi] = (uint32_t)((r & 7) << 4);
    }
    const uint32_t aCol = (uint32_t)(cA16 * 16);
    const int nB = (lane & 7) + ((lane & 16) ? 8 : 0);
    uint32_t bOff[2];
#pragma unroll
    for (int nj = 0; nj < 2; nj++) bOff[nj] = (uint32_t)((n0 + nj * 16 + nB) * 128);
    const uint32_t bXor = (uint32_t)((lane & 7) << 4);
    const uint32_t bCol = (lane & 8) ? 16u : 0u;
    const uint32_t base = smem_u32(buf);

    float acc[2][4][4];
#pragma unroll
    for (int mi = 0; mi < 2; mi++)
#pragma unroll
        for (int nt = 0; nt < 4; nt++)
#pragma unroll
            for (int e = 0; e < 4; e++) acc[mi][nt][e] = 0.f;

    float vreg[16];
    {
        const float* src = W + (size_t)(b * 3) * CH * K_LAT;
#pragma unroll
        for (int it = 0; it < 16; it++) vreg[it] = src[it * 512 + t];
    }

    for (int cc = 0; cc < 3; cc++) {
        const int ch = b * 3 + cc;
#pragma unroll
        for (int it = 0; it < 16; it++) {
            int l = it * 512 + t;
            int rr = l >> 7, n = l & 127;
            unsigned off = (unsigned)(n * 128 + ((rr * 2) ^ ((n & 7) << 4)));
            *reinterpret_cast<__nv_bfloat16*>(&buf[off]) = __float2bfloat16(vreg[it]);
        }
        __syncthreads();
        if (cc + 1 < 3) {
            const float* src = W + (size_t)(ch + 1) * CH * K_LAT;
#pragma unroll
            for (int it = 0; it < 16; it++) vreg[it] = src[it * 512 + t];
        }
        {
            const uint4* s4 = reinterpret_cast<const uint4*>(buf);
            uint4* d4 = reinterpret_cast<uint4*>(g_Wt_sw) + ch * 1024;
            d4[t] = s4[t];
            d4[512 + t] = s4[512 + t];
        }
#pragma unroll
        for (int ks = 0; ks < 4; ks++) {
            const uint32_t kb = (uint32_t)(ks * 32);
            uint32_t a[2][4], b4[2][4];
#pragma unroll
            for (int mi = 0; mi < 2; mi++)
                LDMX4(a[mi], base + aOff[mi] + ((aCol + kb) ^ aXor[mi]));
#pragma unroll
            for (int nj = 0; nj < 2; nj++)
                LDMX4(b4[nj], base + bOff[nj] + ((bCol + kb) ^ bXor));
#pragma unroll
            for (int mi = 0; mi < 2; mi++)
#pragma unroll
                for (int nt = 0; nt < 4; nt++)
                    MMA16816(acc[mi][nt], a[mi], b4[nt >> 1][2 * (nt & 1)], b4[nt >> 1][2 * (nt & 1) + 1]);
        }
        __syncthreads();
    }
    float* outp = g_Mpart + (size_t)b * (K_LAT * K_LAT);
#pragma unroll
    for (int mi = 0; mi < 2; mi++)
#pragma unroll
        for (int nt = 0; nt < 4; nt++) {
            int m = m0 + mi * 16 + (lane >> 2);
            int n = n0 + nt * 8 + 2 * (lane & 3);
            outp[m * K_LAT + n]     = acc[mi][nt][0];
            outp[m * K_LAT + n + 1] = acc[mi][nt][1];
            outp[(m + 8) * K_LAT + n]     = acc[mi][nt][2];
            outp[(m + 8) * K_LAT + n + 1] = acc[mi][nt][3];
        }
}

// ============ k_reduce: fold 16 partials -> g_M (64 blocks x 256 threads) ============
__global__ __launch_bounds__(256) void k_reduce() {
    int idx = blockIdx.x * 256 + threadIdx.x;    // 0..16383
    float s = 0.f;
#pragma unroll
    for (int p = 0; p < GBLK; p++) s += g_Mpart[p * (K_LAT * K_LAT) + idx];
    g_M[idx] = s;
}

// ============ k_invert: rank-2 block Gauss-Jordan, 512 threads ============
// Thread (i, c4): row i (0..127), cols [32*c4, 32*c4+32) as 16 packed f32x2
// registers A2[u] covering cols (2u, 2u+1) of the slice. 64 iterations over
// 2x2 pivot blocks K = {k, k+1}, k = 2*kb. All register indexing is static
// (dynamic indexing demotes to local memory — the R10-R12 bug).
// Rows k,k+1 are published with the KxK block patched to (I + P): consumer
// rows then get their K columns right for free:
//   C + N*(I+P) = C + N + N*P = N   (N = -C*Pinv).
// Pivot rows compute Pinv*[rows] and overwrite their K block with Pinv.
// logdet M = sum log det(P_kb) (block pivots of an SPD matrix, det > 0).
__global__ __launch_bounds__(512, 1) void k_invert(const float* __restrict__ lv) {
    __shared__ __align__(16) unsigned long long rowb[2][2][64];   // [buf][pivot row][64 ULL]
    __shared__ __align__(8)  float2 colb[2][128];                 // [buf][row] = (A[i][k], A[i][k+1])
    __shared__ float detS[64];
    __shared__ float redS[2];
    const int t = threadIdx.x, lane = t & 31;
    const int i = t & 127, c4 = t >> 7;      // c4 in 0..3
    float lv0 = lv[0];
    float sig2 = expf(lv0);

    unsigned long long A2[16];
    {
        const float4* src = reinterpret_cast<const float4*>(g_M + i * K_LAT + c4 * 32);
#pragma unroll
        for (int q = 0; q < 8; q++) {
            float4 v = src[q];
            A2[2 * q]     = pk2(v.x, v.y);
            A2[2 * q + 1] = pk2(v.z, v.w);
        }
    }
    if ((i >> 5) == c4) {
        int kc = i & 31;
#pragma unroll
        for (int u = 0; u < 16; u++) {
            float2 v = upk2(A2[u]);
            if (2 * u == kc)     v.x += sig2;
            if (2 * u + 1 == kc) v.y += sig2;
            A2[u] = pk2(v.x, v.y);
        }
    }

    int buf = 0;
    for (int kb = 0; kb < 64; kb++) {
        const int k  = 2 * kb;
        const int kh = k >> 5;           // owning c4 slice
        const int kp = (k >> 1) & 15;    // ULL index within slice holding cols (k, k+1)
        // publish colb: owner-slice threads write their (col k, col k+1) pair
        if (c4 == kh) {
            unsigned long long cu = 0;
#pragma unroll
            for (int u = 0; u < 16; u++)
                if (u == kp) cu = A2[u];
            colb[buf][i] = upk2(cu);
        }
        // publish rows k, k+1 with K block patched to (I + P)
        if (i == k || i == k + 1) {
            const int r = i - k;   // 0 or 1
#pragma unroll
            for (int j = 0; j < 8; j++) {
                unsigned long long v0 = A2[2 * j], v1 = A2[2 * j + 1];
                if (c4 == kh) {
                    if (2 * j == kp) {
                        float2 w = upk2(v0);
                        if (r == 0) w.x += 1.0f; else w.y += 1.0f;
                        v0 = pk2(w.x, w.y);
                    }
                    if (2 * j + 1 == kp) {
                        float2 w = upk2(v1);
                        if (r == 0) w.x += 1.0f; else w.y += 1.0f;
                        v1 = pk2(w.x, w.y);
                    }
                }
                *reinterpret_cast<ulonglong2*>(&rowb[buf][r][c4 * 16 + 2 * j]) =
                    make_ulonglong2(v0, v1);
            }
        }
        __syncthreads();
        float2 p0 = colb[buf][k];        // (P00, P01)
        float2 p1 = colb[buf][k + 1];    // (P10, P11)
        float det = p0.x * p1.y - p0.y * p1.x;
        float dd = 1.0f / det;
        if (t == 0) detS[kb] = det;
        float i00 =  p1.y * dd, i01 = -p0.y * dd;
        float i10 = -p1.x * dd, i11 =  p0.x * dd;
        if (i == k || i == k + 1) {
            const int r = i - k;
            float a0 = r ? i10 : i00, a1 = r ? i11 : i01;
            unsigned long long a02 = pk2(a0, a0), a12 = pk2(a1, a1);
#pragma unroll
            for (int j = 0; j < 8; j++) {
                ulonglong2 r0 = *reinterpret_cast<const ulonglong2*>(&rowb[buf][0][c4 * 16 + 2 * j]);
                ulonglong2 r1 = *reinterpret_cast<const ulonglong2*>(&rowb[buf][1][c4 * 16 + 2 * j]);
                A2[2 * j]     = ffma2(a12, r1.x, mul2(a02, r0.x));
                A2[2 * j + 1] = ffma2(a12, r1.y, mul2(a02, r0.y));
            }
            if (c4 == kh) {
#pragma unroll
                for (int u = 0; u < 16; u++)
                    if (u == kp) A2[u] = pk2(a0, a1);
            }
        } else {
            float2 cv = colb[buf][i];
            float na = -(cv.x * i00 + cv.y * i10);
            float nb = -(cv.x * i01 + cv.y * i11);
            unsigned long long na2 = pk2(na, na), nb2 = pk2(nb, nb);
#pragma unroll
            for (int j = 0; j < 8; j++) {
                ulonglong2 r0 = *reinterpret_cast<const ulonglong2*>(&rowb[buf][0][c4 * 16 + 2 * j]);
                ulonglong2 r1 = *reinterpret_cast<const ulonglong2*>(&rowb[buf][1][c4 * 16 + 2 * j]);
                A2[2 * j]     = ffma2(nb2, r1.x, ffma2(na2, r0.x, A2[2 * j]));
                A2[2 * j + 1] = ffma2(nb2, r1.y, ffma2(na2, r0.y, A2[2 * j + 1]));
            }
        }
        buf ^= 1;
    }
    // emit bf16 Minv (row-major)
    {
        uint32_t* dst = reinterpret_cast<uint32_t*>(g_Minv_bf) + (i * K_LAT + c4 * 32) / 2;
#pragma unroll
        for (int u = 0; u < 16; u++) {
            float2 v = upk2(A2[u]);
            dst[u] = bfx2(v.x, v.y);
        }
    }
    __syncthreads();
    float ld = 0.f;
    if (t < 64) ld = logf(detS[t]);
#pragma unroll
    for (int off = 16; off > 0; off >>= 1) ld += __shfl_xor_sync(0xffffffffu, ld, off);
    if (t < 64 && lane == 0) redS[t >> 5] = ld;
    __syncthreads();
    if (t == 0) {
        const float LOG2PI = 1.8378770664093453f;
        float logdet = redS[0] + redS[1];
        g_consts[0] = (float)N_FEAT * LOG2PI + (float)(N_FEAT - K_LAT) * lv0 + logdet;
        g_consts[1] = expf(-lv0);
    }
}

// ============ k_main: EXACT R8/R12/R14 kernel (measured 65-66 us, regs 124) ============
// mainloop smem:  A 2x8KB @0, B 2x16KB @16384, mean 12KB @49152, red @61440
// epilogue smem:  Y (pitch 272B, 64 rows) @0, Minv (pitch 272B, 128 rows) @17408
#define SM_A     0
#define SM_B     16384
#define SM_MEAN  49152
#define SM_RED   61440
#define SM_Y     0
#define SM_MI    17408
#define SM_TOTAL 62720

__global__ void __launch_bounds__(256, 2) k_main(const float* __restrict__ ex,
                                                 const float* __restrict__ mean,
                                                 float* __restrict__ out) {
    extern __shared__ __align__(16) unsigned char smem[];
    uint32_t sb = smem_u32(smem);
    const int t = threadIdx.x, lane = t & 31, wid = t >> 5;
    const int wm = wid & 1, wn = wid >> 1;        // warp grid: 2 (M) x 4 (N)
    const int m0 = wm * 32, n0 = wn * 32;

    // cache mean in smem
    float* meanS = reinterpret_cast<float*>(smem + SM_MEAN);
    for (int i = t; i < N_FEAT; i += 256) meanS[i] = mean[i];

    // residual load geometry: 4 threads per row, 16 cols each
    const int row = t >> 2, q = t & 3;
    const float4* exp4 =
        reinterpret_cast<const float4*>(ex + (size_t)(blockIdx.x * MBLK + row) * N_FEAT) + q * 4;
    float4 cur[4];
#pragma unroll
    for (int g = 0; g < 4; g++) cur[g] = exp4[g];

    // ldmatrix lane geometry (SW128, 128B rows)
    const int rA = lane & 15, cA16 = lane >> 4;
    uint32_t aOff[2], aXor[2];
#pragma unroll
    for (int mi = 0; mi < 2; mi++) {
        int r = m0 + mi * 16 + rA;
        aOff[mi] = (uint32_t)(r * 128);
        aXor[mi] = (uint32_t)((r & 7) << 4);
    }
    const uint32_t aCol = (uint32_t)(cA16 * 16);
    const int nB = (lane & 7) + ((lane & 16) ? 8 : 0);
    uint32_t bOff[2];
#pragma unroll
    for (int nj = 0; nj < 2; nj++) bOff[nj] = (uint32_t)((n0 + nj * 16 + nB) * 128);
    const uint32_t bXor = (uint32_t)((lane & 7) << 4);
    const uint32_t bCol = (lane & 8) ? 16u : 0u;

    float acc[2][4][4];
#pragma unroll
    for (int mi = 0; mi < 2; mi++)
#pragma unroll
        for (int nt = 0; nt < 4; nt++)
#pragma unroll
            for (int e = 0; e < 4; e++) acc[mi][nt][e] = 0.f;

    float ssq = 0.f;
    const uint32_t rbase = (uint32_t)(row * 128);
    const uint32_t xr = (uint32_t)((row & 7) << 4);

    for (int c = 0; c < NCH; c++) {
        const int buf = c & 1;
        // B chunk copy (pre-swizzled, L2-resident): 1024 uint4
        {
            const uint4* src = reinterpret_cast<const uint4*>(g_Wt_sw) + c * 1024;
            uint4* dst = reinterpret_cast<uint4*>(smem + SM_B + buf * 16384);
#pragma unroll
            for (int i = 0; i < 4; i++) dst[i * 256 + t] = src[i * 256 + t];
        }
        // A convert: res = ex - mean -> bf16 swizzled; ssq accumulate
        {
            unsigned char* A = smem + SM_A + buf * 8192;
            const float* mS = meanS + c * 64 + q * 16;
#pragma unroll
            for (int g = 0; g < 4; g++) {
                float4 x = cur[g];
                float4 m4 = *reinterpret_cast<const float4*>(mS + g * 4);
                float r0 = x.x - m4.x, r1 = x.y - m4.y, r2 = x.z - m4.z, r3 = x.w - m4.w;
                ssq = fmaf(r0, r0, ssq); ssq = fmaf(r1, r1, ssq);
                ssq = fmaf(r2, r2, ssq); ssq = fmaf(r3, r3, ssq);
                uint32_t off = rbase + (((uint32_t)(q * 32 + g * 8)) ^ xr);
                *reinterpret_cast<uint2*>(A + off) = make_uint2(bfx2(r0, r1), bfx2(r2, r3));
            }
        }
        // prefetch next chunk (overlaps compute via double buffer)
        if (c + 1 < NCH) {
#pragma unroll
            for (int g = 0; g < 4; g++) cur[g] = exp4[(c + 1) * 16 + g];
        }
        __syncthreads();

        const uint32_t A = sb + SM_A + buf * 8192;
        const uint32_t B = sb + SM_B + buf * 16384;
#pragma unroll
        for (int ks = 0; ks < 4; ks++) {
            const uint32_t kb = (uint32_t)(ks * 32);
            uint32_t a[2][4], b4[2][4];
#pragma unroll
            for (int mi = 0; mi < 2; mi++)
                LDMX4(a[mi], A + aOff[mi] + ((aCol + kb) ^ aXor[mi]));
#pragma unroll
            for (int nj = 0; nj < 2; nj++)
                LDMX4(b4[nj], B + bOff[nj] + ((bCol + kb) ^ bXor));
#pragma unroll
            for (int mi = 0; mi < 2; mi++)
#pragma unroll
                for (int nt = 0; nt < 4; nt++)
                    MMA16816(acc[mi][nt], a[mi], b4[nt >> 1][2 * (nt & 1)], b4[nt >> 1][2 * (nt & 1) + 1]);
        }
    }

    // ssq: reduce 4 threads per row
    ssq += __shfl_xor_sync(0xffffffffu, ssq, 1);
    ssq += __shfl_xor_sync(0xffffffffu, ssq, 2);
    float* ssqS = reinterpret_cast<float*>(smem + SM_RED);
    if ((lane & 3) == 0) ssqS[wid * 8 + (lane >> 2)] = ssq;
    __syncthreads();   // all mainloop smem reads done; safe to overwrite with Y/Minv

    // ---- epilogue: stage Y bf16 (pitch 272), copy Minv bf16 (pitch 272) ----
#pragma unroll
    for (int mi = 0; mi < 2; mi++)
#pragma unroll
        for (int nt = 0; nt < 4; nt++) {
            int m = m0 + mi * 16 + (lane >> 2);
            int n = n0 + nt * 8 + 2 * (lane & 3);
            *reinterpret_cast<uint32_t*>(smem + SM_Y + m * 272 + n * 2) =
                bfx2(acc[mi][nt][0], acc[mi][nt][1]);
            *reinterpret_cast<uint32_t*>(smem + SM_Y + (m + 8) * 272 + n * 2) =
                bfx2(acc[mi][nt][2], acc[mi][nt][3]);
        }
    {
        const uint4* msrc = reinterpret_cast<const uint4*>(g_Minv_bf);
#pragma unroll
        for (int i = 0; i < 8; i++) {
            int idx = i * 256 + t;
            int r = idx >> 4, cc = idx & 15;
            *reinterpret_cast<uint4*>(smem + SM_MI + r * 272 + cc * 16) = msrc[idx];
        }
    }
    __syncthreads();

    // ---- second GEMM: Q = Y(64x128) @ Minv(128x128) ----
    float acc2[2][4][4];
#pragma unroll
    for (int mi = 0; mi < 2; mi++)
#pragma unroll
        for (int nt = 0; nt < 4; nt++)
#pragma unroll
            for (int e = 0; e < 4; e++) acc2[mi][nt][e] = 0.f;

    uint32_t yRow[2], miRow[2];
#pragma unroll
    for (int mi = 0; mi < 2; mi++)
        yRow[mi] = (uint32_t)(SM_Y + (m0 + mi * 16 + rA) * 272) + aCol;
#pragma unroll
    for (int nj = 0; nj < 2; nj++)
        miRow[nj] = (uint32_t)(SM_MI + (n0 + nj * 16 + nB) * 272) + bCol;

#pragma unroll
    for (int ks = 0; ks < 8; ks++) {
        const uint32_t kb = (uint32_t)(ks * 32);
        uint32_t a[2][4], b4[2][4];
#pragma unroll
        for (int mi = 0; mi < 2; mi++) LDMX4(a[mi], sb + yRow[mi] + kb);
#pragma unroll
        for (int nj = 0; nj < 2; nj++) LDMX4(b4[nj], sb + miRow[nj] + kb);
#pragma unroll
        for (int mi = 0; mi < 2; mi++)
#pragma unroll
            for (int nt = 0; nt < 4; nt++)
                MMA16816(acc2[mi][nt], a[mi], b4[nt >> 1][2 * (nt & 1)], b4[nt >> 1][2 * (nt & 1) + 1]);
    }

    // ---- dot[m] = sum_j Y[m][j] * Q[m][j] (Y re-read with FULL A-frag addressing) ----
    float* ssqS2 = reinterpret_cast<float*>(smem + SM_RED);
    float* dotS = ssqS2 + 64;     // [4][64]
#pragma unroll
    for (int mi = 0; mi < 2; mi++) {
        float dd0 = 0.f, dd1 = 0.f;
#pragma unroll
        for (int jc = 0; jc < 2; jc++) {
            uint32_t ya[4];
            LDMX4(ya, sb + yRow[mi] + (uint32_t)(n0 * 2 + jc * 32));
#pragma unroll
            for (int h = 0; h < 2; h++) {
                int nt = jc * 2 + h;
                float2 y0 = ubfx2(ya[h * 2 + 0]);
                float2 y1 = ubfx2(ya[h * 2 + 1]);
                dd0 += acc2[mi][nt][0] * y0.x + acc2[mi][nt][1] * y0.y;
                dd1 += acc2[mi][nt][2] * y1.x + acc2[mi][nt][3] * y1.y;
            }
        }
        dd0 += __shfl_xor_sync(0xffffffffu, dd0, 1);
        dd0 += __shfl_xor_sync(0xffffffffu, dd0, 2);
        dd1 += __shfl_xor_sync(0xffffffffu, dd1, 1);
        dd1 += __shfl_xor_sync(0xffffffffu, dd1, 2);
        if ((lane & 3) == 0) {
            int m = m0 + mi * 16 + (lane >> 2);
            dotS[wn * 64 + m] = dd0;
            dotS[wn * 64 + m + 8] = dd1;
        }
    }
    __syncthreads();

    if (t < MBLK) {
        float dot = dotS[t] + dotS[64 + t] + dotS[128 + t] + dotS[192 + t];
        float c0 = g_consts[0], is2 = g_consts[1];
        out[blockIdx.x * MBLK + t] = -0.5f * (c0 + (ssqS2[t] - dot) * is2);
    }
}

// ---------------- launch ----------------
extern "C" void kernel_launch(void* const* d_in, const int* in_sizes, int n_in,
                              void* d_out, int out_size) {
    const float* ex = nullptr;
    const float* W = nullptr;
    const float* lv = nullptr;
    const float* mean = nullptr;
    for (int t = 0; t < n_in; t++) {
        if (in_sizes[t] == BATCH * N_FEAT)      ex   = (const float*)d_in[t];
        else if (in_sizes[t] == N_FEAT * K_LAT) W    = (const float*)d_in[t];
        else if (in_sizes[t] == N_FEAT)         mean = (const float*)d_in[t];
        else if (in_sizes[t] == 1)              lv   = (const float*)d_in[t];
    }
    float* out = (float*)d_out;

    cudaFuncSetAttribute(k_main, cudaFuncAttributeMaxDynamicSharedMemorySize, SM_TOTAL);

    k_gram<<<GBLK, 512>>>(W);
    k_reduce<<<K_LAT * K_LAT / 256, 256>>>();
    k_invert<<<1, 512>>>(lv);
    k_main<<<BATCH / MBLK, 256, SM_TOTAL>>>(ex, mean, out);
}

// round 17
// speedup vs baseline: 2.6385x; 1.2653x over previous
#include <cuda_runtime.h>
#include <cuda_bf16.h>
#include <cstdint>
#include <cstddef>

#define N_FEAT 3072
#define K_LAT  128
#define BATCH  8192
#define CH     64
#define NCH    48          /* 3072 / 64 */
#define MBLK   64
#define GBLK   16          /* gram blocks, 3 chunks each */

// ---------------- device scratch (static — no allocations) ----------------
__device__ float g_Mpart[GBLK * K_LAT * K_LAT];                     // 1 MB gram partials
__device__ float g_M[K_LAT * K_LAT];                                // reduced gram
__device__ float g_consts[2];                                       // [0]=n log2pi+logdetC, [1]=1/sigma^2
__device__ int   g_flag;                                            // Minv-ready flag
__device__ __align__(16) __nv_bfloat16 g_Wt_sw[NCH * K_LAT * CH];   // 768 KB, per-chunk SW128 W^T
__device__ __align__(16) __nv_bfloat16 g_Minv_bf[K_LAT * K_LAT];    // 32 KB, row-major bf16 Minv

static __device__ __forceinline__ uint32_t smem_u32(const void* p) {
    uint32_t a;
    asm("{ .reg .u64 t; cvta.to.shared.u64 t, %1; cvt.u32.u64 %0, t; }" : "=r"(a) : "l"(p));
    return a;
}

#define LDMX4(r, addr) \
    asm volatile("ldmatrix.sync.aligned.m8n8.x4.shared.b16 {%0,%1,%2,%3}, [%4];" \
        : "=r"((r)[0]), "=r"((r)[1]), "=r"((r)[2]), "=r"((r)[3]) : "r"(addr))

#define MMA16816(d, a, b0, b1) \
    asm volatile("mma.sync.aligned.m16n8k16.row.col.f32.bf16.bf16.f32 " \
        "{%0,%1,%2,%3}, {%4,%5,%6,%7}, {%8,%9}, {%0,%1,%2,%3};" \
        : "+f"((d)[0]), "+f"((d)[1]), "+f"((d)[2]), "+f"((d)[3]) \
        : "r"((a)[0]), "r"((a)[1]), "r"((a)[2]), "r"((a)[3]), "r"(b0), "r"(b1))

static __device__ __forceinline__ uint32_t bfx2(float a, float b) {
    __nv_bfloat162 h = __floats2bfloat162_rn(a, b);
    return *reinterpret_cast<uint32_t*>(&h);
}
static __device__ __forceinline__ float2 ubfx2(uint32_t v) {
    float2 r;
    r.x = __uint_as_float(v << 16);
    r.y = __uint_as_float(v & 0xffff0000u);
    return r;
}
static __device__ __forceinline__ unsigned long long pk2(float x, float y) {
    unsigned long long r;
    asm("mov.b64 %0, {%1,%2};" : "=l"(r) : "f"(x), "f"(y));
    return r;
}
static __device__ __forceinline__ float2 upk2(unsigned long long v) {
    float2 r;
    asm("mov.b64 {%0,%1}, %2;" : "=f"(r.x), "=f"(r.y) : "l"(v));
    return r;
}
static __device__ __forceinline__ unsigned long long ffma2(
    unsigned long long a, unsigned long long b, unsigned long long c) {
    unsigned long long d;
    asm("fma.rn.f32x2 %0, %1, %2, %3;" : "=l"(d) : "l"(a), "l"(b), "l"(c));
    return d;
}
static __device__ __forceinline__ unsigned long long mul2(
    unsigned long long a, unsigned long long b) {
    unsigned long long d;
    asm("mul.rn.f32x2 %0, %1, %2;" : "=l"(d) : "l"(a), "l"(b));
    return d;
}

// ============ k_gram: build SW128 bf16 W^T chunks + MMA gram partials ============
__global__ __launch_bounds__(512) void k_gram(const float* __restrict__ W) {
    __shared__ __align__(16) unsigned char buf[K_LAT * CH * 2];   // 16 KB, one chunk
    const int t = threadIdx.x, lane = t & 31, wid = t >> 5;
    const int b = blockIdx.x;
    const int wm = wid & 3, wn = wid >> 2;
    const int m0 = wm * 32, n0 = wn * 32;
    const int rA = lane & 15, cA16 = lane >> 4;
    uint32_t aOff[2], aXor[2];
#pragma unroll
    for (int mi = 0; mi < 2; mi++) {
        int r = m0 + mi * 16 + rA;
        aOff[mi] = (uint32_t)(r * 128);
        aXor[mi] = (uint32_t)((r & 7) << 4);
    }
    const uint32_t aCol = (uint32_t)(cA16 * 16);
    const int nB = (lane & 7) + ((lane & 16) ? 8 : 0);
    uint32_t bOff[2];
#pragma unroll
    for (int nj = 0; nj < 2; nj++) bOff[nj] = (uint32_t)((n0 + nj * 16 + nB) * 128);
    const uint32_t bXor = (uint32_t)((lane & 7) << 4);
    const uint32_t bCol = (lane & 8) ? 16u : 0u;
    const uint32_t base = smem_u32(buf);

    float acc[2][4][4];
#pragma unroll
    for (int mi = 0; mi < 2; mi++)
#pragma unroll
        for (int nt = 0; nt < 4; nt++)
#pragma unroll
            for (int e = 0; e < 4; e++) acc[mi][nt][e] = 0.f;

    float vreg[16];
    {
        const float* src = W + (size_t)(b * 3) * CH * K_LAT;
#pragma unroll
        for (int it = 0; it < 16; it++) vreg[it] = src[it * 512 + t];
    }

    for (int cc = 0; cc < 3; cc++) {
        const int ch = b * 3 + cc;
#pragma unroll
        for (int it = 0; it < 16; it++) {
            int l = it * 512 + t;
            int rr = l >> 7, n = l & 127;
            unsigned off = (unsigned)(n * 128 + ((rr * 2) ^ ((n & 7) << 4)));
            *reinterpret_cast<__nv_bfloat16*>(&buf[off]) = __float2bfloat16(vreg[it]);
        }
        __syncthreads();
        if (cc + 1 < 3) {
            const float* src = W + (size_t)(ch + 1) * CH * K_LAT;
#pragma unroll
            for (int it = 0; it < 16; it++) vreg[it] = src[it * 512 + t];
        }
        {
            const uint4* s4 = reinterpret_cast<const uint4*>(buf);
            uint4* d4 = reinterpret_cast<uint4*>(g_Wt_sw) + ch * 1024;
            d4[t] = s4[t];
            d4[512 + t] = s4[512 + t];
        }
#pragma unroll
        for (int ks = 0; ks < 4; ks++) {
            const uint32_t kb = (uint32_t)(ks * 32);
            uint32_t a[2][4], b4[2][4];
#pragma unroll
            for (int mi = 0; mi < 2; mi++)
                LDMX4(a[mi], base + aOff[mi] + ((aCol + kb) ^ aXor[mi]));
#pragma unroll
            for (int nj = 0; nj < 2; nj++)
                LDMX4(b4[nj], base + bOff[nj] + ((bCol + kb) ^ bXor));
#pragma unroll
            for (int mi = 0; mi < 2; mi++)
#pragma unroll
                for (int nt = 0; nt < 4; nt++)
                    MMA16816(acc[mi][nt], a[mi], b4[nt >> 1][2 * (nt & 1)], b4[nt >> 1][2 * (nt & 1) + 1]);
        }
        __syncthreads();
    }
    float* outp = g_Mpart + (size_t)b * (K_LAT * K_LAT);
#pragma unroll
    for (int mi = 0; mi < 2; mi++)
#pragma unroll
        for (int nt = 0; nt < 4; nt++) {
            int m = m0 + mi * 16 + (lane >> 2);
            int n = n0 + nt * 8 + 2 * (lane & 3);
            outp[m * K_LAT + n]     = acc[mi][nt][0];
            outp[m * K_LAT + n + 1] = acc[mi][nt][1];
            outp[(m + 8) * K_LAT + n]     = acc[mi][nt][2];
            outp[(m + 8) * K_LAT + n + 1] = acc[mi][nt][3];
        }
}

// ============ k_reduce: fold 16 partials -> g_M (64 blocks x 256 threads) ============
__global__ __launch_bounds__(256) void k_reduce() {
    int idx = blockIdx.x * 256 + threadIdx.x;    // 0..16383
    float s = 0.f;
#pragma unroll
    for (int p = 0; p < GBLK; p++) s += g_Mpart[p * (K_LAT * K_LAT) + idx];
    g_M[idx] = s;
}

// ============ k_main: block 0 = rank-2 GJ inverter; blocks 1..128 = mainloop ============
// mainloop smem:  A 2x8KB @0, B 2x16KB @16384, mean 12KB @49152, red @61440
// epilogue smem:  Y (pitch 272B, 64 rows) @0, Minv (pitch 272B, 128 rows) @17408
#define SM_A     0
#define SM_B     16384
#define SM_MEAN  49152
#define SM_RED   61440
#define SM_Y     0
#define SM_MI    17408
#define SM_TOTAL 62720

__global__ void __launch_bounds__(256, 2) k_main(const float* __restrict__ ex,
                                                 const float* __restrict__ mean,
                                                 const float* __restrict__ lv,
                                                 float* __restrict__ out) {
    extern __shared__ __align__(16) unsigned char smem[];
    uint32_t sb = smem_u32(smem);
    const int t = threadIdx.x, lane = t & 31, wid = t >> 5;

    if (blockIdx.x == 0) {
        // ---------- inverter block: 256 threads, rank-2 block Gauss-Jordan ----------
        // Thread (i, c2): row i, cols [64*c2, 64*c2+64) as 32 packed f32x2 regs.
        // All register indexing static (dynamic indexing demotes to local mem).
        // Pivot rows published with K block patched to (I + P): consumers get
        // column-K correctness for free (C + N*(I+P) = N, N = -C*Pinv).
        unsigned long long* rowb = reinterpret_cast<unsigned long long*>(smem); // [2][2][64]
        float2* colb = reinterpret_cast<float2*>(smem + 2048);                   // [2][128]
        float* detS = reinterpret_cast<float*>(smem + 4096);                     // [64]
        float* redS = reinterpret_cast<float*>(smem + 4352);                     // [2]
        const int i = t & 127, c2 = t >> 7;        // c2 in {0,1}
        float lv0 = lv[0];
        float sig2 = expf(lv0);

        unsigned long long A2[32];
        {
            const float4* src = reinterpret_cast<const float4*>(g_M + i * K_LAT + c2 * 64);
#pragma unroll
            for (int q = 0; q < 16; q++) {
                float4 v = src[q];
                A2[2 * q]     = pk2(v.x, v.y);
                A2[2 * q + 1] = pk2(v.z, v.w);
            }
        }
        if ((i >> 6) == c2) {
            int kc = i & 63;
#pragma unroll
            for (int u = 0; u < 32; u++) {
                float2 v = upk2(A2[u]);
                if (2 * u == kc)     v.x += sig2;
                if (2 * u + 1 == kc) v.y += sig2;
                A2[u] = pk2(v.x, v.y);
            }
        }

        int buf = 0;
        for (int kb = 0; kb < 64; kb++) {
            const int k  = 2 * kb;
            const int kh = k >> 6;           // owning c2 slice
            const int kp = (k >> 1) & 31;    // ULL index within slice holding cols (k, k+1)
            if (c2 == kh) {
                unsigned long long cu = 0;
#pragma unroll
                for (int u = 0; u < 32; u++)
                    if (u == kp) cu = A2[u];
                colb[buf * 128 + i] = upk2(cu);
            }
            if (i == k || i == k + 1) {
                const int r = i - k;   // 0 or 1
#pragma unroll
                for (int j = 0; j < 16; j++) {
                    unsigned long long v0 = A2[2 * j], v1 = A2[2 * j + 1];
                    if (c2 == kh) {
                        if (2 * j == kp) {
                            float2 w = upk2(v0);
                            if (r == 0) w.x += 1.0f; else w.y += 1.0f;
                            v0 = pk2(w.x, w.y);
                        }
                        if (2 * j + 1 == kp) {
                            float2 w = upk2(v1);
                            if (r == 0) w.x += 1.0f; else w.y += 1.0f;
                            v1 = pk2(w.x, w.y);
                        }
                    }
                    *reinterpret_cast<ulonglong2*>(&rowb[buf * 128 + r * 64 + c2 * 32 + 2 * j]) =
                        make_ulonglong2(v0, v1);
                }
            }
            __syncthreads();
            float2 p0 = colb[buf * 128 + k];
            float2 p1 = colb[buf * 128 + k + 1];
            float det = p0.x * p1.y - p0.y * p1.x;
            float dd = 1.0f / det;
            if (t == 0) detS[kb] = det;
            float i00 =  p1.y * dd, i01 = -p0.y * dd;
            float i10 = -p1.x * dd, i11 =  p0.x * dd;
            if (i == k || i == k + 1) {
                const int r = i - k;
                float a0 = r ? i10 : i00, a1 = r ? i11 : i01;
                unsigned long long a02 = pk2(a0, a0), a12 = pk2(a1, a1);
#pragma unroll
                for (int j = 0; j < 16; j++) {
                    ulonglong2 r0 = *reinterpret_cast<const ulonglong2*>(
                        &rowb[buf * 128 + 0 * 64 + c2 * 32 + 2 * j]);
                    ulonglong2 r1 = *reinterpret_cast<const ulonglong2*>(
                        &rowb[buf * 128 + 1 * 64 + c2 * 32 + 2 * j]);
                    A2[2 * j]     = ffma2(a12, r1.x, mul2(a02, r0.x));
                    A2[2 * j + 1] = ffma2(a12, r1.y, mul2(a02, r0.y));
                }
                if (c2 == kh) {
#pragma unroll
                    for (int u = 0; u < 32; u++)
                        if (u == kp) A2[u] = pk2(a0, a1);
                }
            } else {
                float2 cv = colb[buf * 128 + i];
                float na = -(cv.x * i00 + cv.y * i10);
                float nb = -(cv.x * i01 + cv.y * i11);
                unsigned long long na2 = pk2(na, na), nb2 = pk2(nb, nb);
#pragma unroll
                for (int j = 0; j < 16; j++) {
                    ulonglong2 r0 = *reinterpret_cast<const ulonglong2*>(
                        &rowb[buf * 128 + 0 * 64 + c2 * 32 + 2 * j]);
                    ulonglong2 r1 = *reinterpret_cast<const ulonglong2*>(
                        &rowb[buf * 128 + 1 * 64 + c2 * 32 + 2 * j]);
                    A2[2 * j]     = ffma2(nb2, r1.x, ffma2(na2, r0.x, A2[2 * j]));
                    A2[2 * j + 1] = ffma2(nb2, r1.y, ffma2(na2, r0.y, A2[2 * j + 1]));
                }
            }
            buf ^= 1;
        }
        // emit bf16 Minv (row-major)
        {
            uint32_t* dst = reinterpret_cast<uint32_t*>(g_Minv_bf) + (i * K_LAT + c2 * 64) / 2;
#pragma unroll
            for (int u = 0; u < 32; u++) {
                float2 v = upk2(A2[u]);
                dst[u] = bfx2(v.x, v.y);
            }
        }
        __syncthreads();
        float ld = 0.f;
        if (t < 64) ld = logf(detS[t]);
#pragma unroll
        for (int off = 16; off > 0; off >>= 1) ld += __shfl_xor_sync(0xffffffffu, ld, off);
        if (t < 64 && lane == 0) redS[t >> 5] = ld;
        __syncthreads();
        if (t == 0) {
            const float LOG2PI = 1.8378770664093453f;
            float logdet = redS[0] + redS[1];
            g_consts[0] = (float)N_FEAT * LOG2PI + (float)(N_FEAT - K_LAT) * lv0 + logdet;
            g_consts[1] = expf(-lv0);
        }
        __syncthreads();
        __threadfence();
        if (t == 0)
            asm volatile("st.global.release.gpu.b32 [%0], %1;" :: "l"(&g_flag), "r"(1) : "memory");
        return;
    }

    // ---------- mainloop blocks (bid 1..128), R8-proven geometry ----------
    const int bid = blockIdx.x - 1;
    const int wm = wid & 1, wn = wid >> 1;        // warp grid: 2 (M) x 4 (N)
    const int m0 = wm * 32, n0 = wn * 32;

    // cache mean in smem
    float* meanS = reinterpret_cast<float*>(smem + SM_MEAN);
    for (int i = t; i < N_FEAT; i += 256) meanS[i] = mean[i];

    // residual load geometry: 4 threads per row, 16 cols each
    const int row = t >> 2, q = t & 3;
    const float4* exp4 =
        reinterpret_cast<const float4*>(ex + (size_t)(bid * MBLK + row) * N_FEAT) + q * 4;
    float4 cur[4];
#pragma unroll
    for (int g = 0; g < 4; g++) cur[g] = exp4[g];

    // ldmatrix lane geometry (SW128, 128B rows)
    const int rA = lane & 15, cA16 = lane >> 4;
    uint32_t aOff[2], aXor[2];
#pragma unroll
    for (int mi = 0; mi < 2; mi++) {
        int r = m0 + mi * 16 + rA;
        aOff[mi] = (uint32_t)(r * 128);
        aXor[mi] = (uint32_t)((r & 7) << 4);
    }
    const uint32_t aCol = (uint32_t)(cA16 * 16);
    const int nB = (lane & 7) + ((lane & 16) ? 8 : 0);
    uint32_t bOff[2];
#pragma unroll
    for (int nj = 0; nj < 2; nj++) bOff[nj] = (uint32_t)((n0 + nj * 16 + nB) * 128);
    const uint32_t bXor = (uint32_t)((lane & 7) << 4);
    const uint32_t bCol = (lane & 8) ? 16u : 0u;

    float acc[2][4][4];
#pragma unroll
    for (int mi = 0; mi < 2; mi++)
#pragma unroll
        for (int nt = 0; nt < 4; nt++)
#pragma unroll
            for (int e = 0; e < 4; e++) acc[mi][nt][e] = 0.f;

    float ssq = 0.f;
    const uint32_t rbase = (uint32_t)(row * 128);
    const uint32_t xr = (uint32_t)((row & 7) << 4);

    for (int c = 0; c < NCH; c++) {
        const int buf = c & 1;
        // B chunk copy (pre-swizzled, L2-resident): 1024 uint4
        {
            const uint4* src = reinterpret_cast<const uint4*>(g_Wt_sw) + c * 1024;
            uint4* dst = reinterpret_cast<uint4*>(smem + SM_B + buf * 16384);
#pragma unroll
            for (int i = 0; i < 4; i++) dst[i * 256 + t] = src[i * 256 + t];
        }
        // A convert: res = ex - mean -> bf16 swizzled; ssq accumulate
        {
            unsigned char* A = smem + SM_A + buf * 8192;
            const float* mS = meanS + c * 64 + q * 16;
#pragma unroll
            for (int g = 0; g < 4; g++) {
                float4 x = cur[g];
                float4 m4 = *reinterpret_cast<const float4*>(mS + g * 4);
                float r0 = x.x - m4.x, r1 = x.y - m4.y, r2 = x.z - m4.z, r3 = x.w - m4.w;
                ssq = fmaf(r0, r0, ssq); ssq = fmaf(r1, r1, ssq);
                ssq = fmaf(r2, r2, ssq); ssq = fmaf(r3, r3, ssq);
                uint32_t off = rbase + (((uint32_t)(q * 32 + g * 8)) ^ xr);
                *reinterpret_cast<uint2*>(A + off) = make_uint2(bfx2(r0, r1), bfx2(r2, r3));
            }
        }
        // prefetch next chunk (overlaps compute via double buffer)
        if (c + 1 < NCH) {
#pragma unroll
            for (int g = 0; g < 4; g++) cur[g] = exp4[(c + 1) * 16 + g];
        }
        __syncthreads();

        const uint32_t A = sb + SM_A + buf * 8192;
        const uint32_t B = sb + SM_B + buf * 16384;
#pragma unroll
        for (int ks = 0; ks < 4; ks++) {
            const uint32_t kb = (uint32_t)(ks * 32);
            uint32_t a[2][4], b4[2][4];
#pragma unroll
            for (int mi = 0; mi < 2; mi++)
                LDMX4(a[mi], A + aOff[mi] + ((aCol + kb) ^ aXor[mi]));
#pragma unroll
            for (int nj = 0; nj < 2; nj++)
                LDMX4(b4[nj], B + bOff[nj] + ((bCol + kb) ^ bXor));
#pragma unroll
            for (int mi = 0; mi < 2; mi++)
#pragma unroll
                for (int nt = 0; nt < 4; nt++)
                    MMA16816(acc[mi][nt], a[mi], b4[nt >> 1][2 * (nt & 1)], b4[nt >> 1][2 * (nt & 1) + 1]);
        }
    }

    // ssq: reduce 4 threads per row
    ssq += __shfl_xor_sync(0xffffffffu, ssq, 1);
    ssq += __shfl_xor_sync(0xffffffffu, ssq, 2);
    float* ssqS = reinterpret_cast<float*>(smem + SM_RED);
    if ((lane & 3) == 0) ssqS[wid * 8 + (lane >> 2)] = ssq;
    __syncthreads();   // all mainloop smem reads done; safe to overwrite with Y/Minv

    // ---- epilogue: stage Y bf16 (pitch 272) ----
#pragma unroll
    for (int mi = 0; mi < 2; mi++)
#pragma unroll
        for (int nt = 0; nt < 4; nt++) {
            int m = m0 + mi * 16 + (lane >> 2);
            int n = n0 + nt * 8 + 2 * (lane & 3);
            *reinterpret_cast<uint32_t*>(smem + SM_Y + m * 272 + n * 2) =
                bfx2(acc[mi][nt][0], acc[mi][nt][1]);
            *reinterpret_cast<uint32_t*>(smem + SM_Y + (m + 8) * 272 + n * 2) =
                bfx2(acc[mi][nt][2], acc[mi][nt][3]);
        }
    // wait for Minv (block 0); inverter (~50us) < mainloop (~60us), so ~no wait
    if (t == 0) {
        unsigned f;
        do {
            asm volatile("ld.global.acquire.gpu.b32 %0, [%1];" : "=r"(f) : "l"(&g_flag) : "memory");
            if (!f) __nanosleep(64);
        } while (!f);
    }
    __syncthreads();
    // copy Minv (pitch 272)
    {
        const uint4* msrc = reinterpret_cast<const uint4*>(g_Minv_bf);
#pragma unroll
        for (int i = 0; i < 8; i++) {
            int idx = i * 256 + t;
            int r = idx >> 4, cc = idx & 15;
            *reinterpret_cast<uint4*>(smem + SM_MI + r * 272 + cc * 16) = msrc[idx];
        }
    }
    __syncthreads();

    // ---- second GEMM: Q = Y(64x128) @ Minv(128x128) ----
    float acc2[2][4][4];
#pragma unroll
    for (int mi = 0; mi < 2; mi++)
#pragma unroll
        for (int nt = 0; nt < 4; nt++)
#pragma unroll
            for (int e = 0; e < 4; e++) acc2[mi][nt][e] = 0.f;

    uint32_t yRow[2], miRow[2];
#pragma unroll
    for (int mi = 0; mi < 2; mi++)
        yRow[mi] = (uint32_t)(SM_Y + (m0 + mi * 16 + rA) * 272) + aCol;
#pragma unroll
    for (int nj = 0; nj < 2; nj++)
        miRow[nj] = (uint32_t)(SM_MI + (n0 + nj * 16 + nB) * 272) + bCol;

#pragma unroll
    for (int ks = 0; ks < 8; ks++) {
        const uint32_t kb = (uint32_t)(ks * 32);
        uint32_t a[2][4], b4[2][4];
#pragma unroll
        for (int mi = 0; mi < 2; mi++) LDMX4(a[mi], sb + yRow[mi] + kb);
#pragma unroll
        for (int nj = 0; nj < 2; nj++) LDMX4(b4[nj], sb + miRow[nj] + kb);
#pragma unroll
        for (int mi = 0; mi < 2; mi++)
#pragma unroll
            for (int nt = 0; nt < 4; nt++)
                MMA16816(acc2[mi][nt], a[mi], b4[nt >> 1][2 * (nt & 1)], b4[nt >> 1][2 * (nt & 1) + 1]);
    }

    // ---- dot[m] = sum_j Y[m][j] * Q[m][j] (Y re-read with FULL A-frag addressing) ----
    float* ssqS2 = reinterpret_cast<float*>(smem + SM_RED);
    float* dotS = ssqS2 + 64;     // [4][64]
#pragma unroll
    for (int mi = 0; mi < 2; mi++) {
        float dd0 = 0.f, dd1 = 0.f;
#pragma unroll
        for (int jc = 0; jc < 2; jc++) {
            uint32_t ya[4];
            LDMX4(ya, sb + yRow[mi] + (uint32_t)(n0 * 2 + jc * 32));
#pragma unroll
            for (int h = 0; h < 2; h++) {
                int nt = jc * 2 + h;
                float2 y0 = ubfx2(ya[h * 2 + 0]);
                float2 y1 = ubfx2(ya[h * 2 + 1]);
                dd0 += acc2[mi][nt][0] * y0.x + acc2[mi][nt][1] * y0.y;
                dd1 += acc2[mi][nt][2] * y1.x + acc2[mi][nt][3] * y1.y;
            }
        }
        dd0 += __shfl_xor_sync(0xffffffffu, dd0, 1);
        dd0 += __shfl_xor_sync(0xffffffffu, dd0, 2);
        dd1 += __shfl_xor_sync(0xffffffffu, dd1, 1);
        dd1 += __shfl_xor_sync(0xffffffffu, dd1, 2);
        if ((lane & 3) == 0) {
            int m = m0 + mi * 16 + (lane >> 2);
            dotS[wn * 64 + m] = dd0;
            dotS[wn * 64 + m + 8] = dd1;
        }
    }
    __syncthreads();

    if (t < MBLK) {
        float dot = dotS[t] + dotS[64 + t] + dotS[128 + t] + dotS[192 + t];
        float c0 = g_consts[0], is2 = g_consts[1];
        out[bid * MBLK + t] = -0.5f * (c0 + (ssqS2[t] - dot) * is2);
    }
}

// ---------------- launch ----------------
extern "C" void kernel_launch(void* const* d_in, const int* in_sizes, int n_in,
                              void* d_out, int out_size) {
    const float* ex = nullptr;
    const float* W = nullptr;
    const float* lv = nullptr;
    const float* mean = nullptr;
    for (int t = 0; t < n_in; t++) {
        if (in_sizes[t] == BATCH * N_FEAT)      ex   = (const float*)d_in[t];
        else if (in_sizes[t] == N_FEAT * K_LAT) W    = (const float*)d_in[t];
        else if (in_sizes[t] == N_FEAT)         mean = (const float*)d_in[t];
        else if (in_sizes[t] == 1)              lv   = (const float*)d_in[t];
    }
    float* out = (float*)d_out;

    cudaFuncSetAttribute(k_main, cudaFuncAttributeMaxDynamicSharedMemorySize, SM_TOTAL);

    k_gram<<<GBLK, 512>>>(W);
    k_reduce<<<K_LAT * K_LAT / 256, 256>>>();
    k_main<<<BATCH / MBLK + 1, 256, SM_TOTAL>>>(ex, mean, lv, out);
}